// round 8
// baseline (speedup 1.0000x reference)
#include <cuda_runtime.h>
#include <cuda_bf16.h>
#include <cstdint>

// ParallelLinear: out[b,t,o] = sum_i x[b,t,i] * W[t,o,i] + bias[t,o]
// B=512, T=1024, ISIZE=OSIZE=64, fp32.
// R8: mma.sync bf16-split fp32 (D = Ahi*Bhi + Ahi*Blo + Alo*Bhi).
//   ROWS=64 (one 16-row m-tile per warp) -> ~half the regs -> 6 CTAs/SM,
//   k-permuted LDG.128 x fragments, n-permuted B -> STG.128 epilogue.

#define TT    1024
#define BB    512
#define KK    64
#define OO    64
#define BLOCK 128
#define ROWS  64

typedef unsigned int u32;

// ---- smem byte offsets ----
#define SM_BIAS 0                          // 64 floats = 256 B
#define SM_BHI  256                        // 64 rows * 128 B = 8192
#define SM_BLO  (SM_BHI + OO * 128)
#define SM_TOTAL (SM_BLO + OO * 128)       // 16640

__device__ __forceinline__ u32 smem_u32(const void* p) {
    u32 a;
    asm("{ .reg .u64 t; cvta.to.shared.u64 t, %1; cvt.u32.u64 %0, t; }" : "=r"(a) : "l"(p));
    return a;
}

// split fp32 pair -> packed bf16x2 hi and lo
__device__ __forceinline__ void split2(float ax, float ay, u32 &hi, u32 &lo) {
    float2 v = { ax, ay };
    __nv_bfloat162 hp = __float22bfloat162_rn(v);
    u32 h = *(u32*)&hp;
    float hx = __uint_as_float(h << 16);
    float hy = __uint_as_float(h & 0xFFFF0000u);
    float2 r = { v.x - hx, v.y - hy };
    __nv_bfloat162 lp = __float22bfloat162_rn(r);
    hi = h;
    lo = *(u32*)&lp;
}

// W staging-write offset with XOR swizzle (row = staged n-position, ip = staged pair idx)
__device__ __forceinline__ u32 stage_off(int row, int ip) {
    return (u32)(row * 128 + ((((ip >> 2) ^ (row & 7)) & 7) << 4) + ((ip & 3) << 2));
}

__device__ __forceinline__ void ldmx4(u32 &r0, u32 &r1, u32 &r2, u32 &r3, u32 addr) {
    asm volatile("ldmatrix.sync.aligned.m8n8.x4.shared.b16 {%0,%1,%2,%3}, [%4];"
                 : "=r"(r0), "=r"(r1), "=r"(r2), "=r"(r3) : "r"(addr));
}

__device__ __forceinline__ void mma_bf16(float* d, const u32* a, u32 b0, u32 b1) {
    asm volatile(
        "mma.sync.aligned.m16n8k16.row.col.f32.bf16.bf16.f32 "
        "{%0,%1,%2,%3}, {%4,%5,%6,%7}, {%8,%9}, {%0,%1,%2,%3};"
        : "+f"(d[0]), "+f"(d[1]), "+f"(d[2]), "+f"(d[3])
        : "r"(a[0]), "r"(a[1]), "r"(a[2]), "r"(a[3]), "r"(b0), "r"(b1));
}

__global__ __launch_bounds__(BLOCK, 6)
void ParallelLinear_59133109732019_kernel(
    const float* __restrict__ x,     // [B, T, 64]
    const float* __restrict__ W,     // [T, 64, 64]  (W[t][o][i])
    const float* __restrict__ bias,  // [T, 64]
    float* __restrict__ out)         // [B, T, 64]
{
    extern __shared__ char smem[];
    const u32 sb = smem_u32(smem);

    const int t       = blockIdx.y;
    const int rowBase = blockIdx.x * ROWS;
    const int tid     = threadIdx.x;
    const int wid     = tid >> 5;
    const int lane    = tid & 31;
    const int g       = lane >> 2;       // row within 8-group
    const int q       = lane & 3;        // fragment column selector

    // x fragment base: rows (rowBase + wid*16 + g [+8]), col 4q (k-permuted)
    const size_t xrstride = (size_t)TT * KK;
    const float* xbase = x + (size_t)(rowBase + wid * 16 + g) * xrstride
                           + (size_t)t * KK + 4 * q;

    // ---- prefetch ks=0 x data (one float4 = one A-fragment half) ----
    float4 xf0 = *(const float4*)(xbase);                  // row g
    float4 xf1 = *(const float4*)(xbase + 8 * xrstride);   // row g+8

    // ---- stage W[t] hi/lo with k-perm (sigma) and n-perm (pi) baked in ----
    {
        const float2* Wg = (const float2*)(W + (size_t)t * (OO * KK));
        #pragma unroll
        for (int k = 0; k < (OO * KK / 2) / BLOCK; k++) {  // 16 iters
            int p = k * BLOCK + tid;
            int o = p >> 5, ip = p & 31;                   // o row, source i-pair
            u32 hi, lo;
            float2 v = Wg[p];
            split2(v.x, v.y, hi, lo);
            // k-perm: pair cp within 16-block -> cp' = (cp&1)*4 + (cp>>1)
            int blk = ip >> 3, cp = ip & 7;
            int ipp = (blk << 3) | (((cp & 1) << 2) | (cp >> 1));
            // n-perm: o = 16m + 4q + 2b + j -> row' = 16m + 8b + 2q + j
            int m = o >> 4, qq = (o >> 2) & 3, bb = (o >> 1) & 1, j = o & 1;
            int rowp = (m << 4) | (bb << 3) | (qq << 1) | j;
            u32 off = stage_off(rowp, ipp);
            *(u32*)(smem + SM_BHI + off) = hi;
            *(u32*)(smem + SM_BLO + off) = lo;
        }
        if (tid < OO) ((float*)(smem + SM_BIAS))[tid] = bias[(size_t)t * OO + tid];
    }
    __syncthreads();

    // ---- accumulators: 8 n-tiles x 4 fp32 ----
    float d[8][4];
    #pragma unroll
    for (int nt = 0; nt < 8; nt++)
        #pragma unroll
        for (int e = 0; e < 4; e++) d[nt][e] = 0.0f;

    // B-fragment ldmatrix lane->address components
    const int b_row  = (lane & 7) + ((lane >> 4) << 3);
    const int b_cadd = (lane >> 3) & 1;

    #pragma unroll
    for (int ks = 0; ks < 4; ks++) {
        // prefetch next k-step's x
        float4 xn0, xn1;
        if (ks < 3) {
            const float* bp = xbase + (ks + 1) * 16;
            xn0 = *(const float4*)(bp);
            xn1 = *(const float4*)(bp + 8 * xrstride);
        }

        // build bf16 hi/lo A fragments (k-permuted: float4 -> R0/R2, R1/R3)
        u32 ah[4], al[4];
        split2(xf0.x, xf0.y, ah[0], al[0]);   // row g,   k-low
        split2(xf1.x, xf1.y, ah[1], al[1]);   // row g+8, k-low
        split2(xf0.z, xf0.w, ah[2], al[2]);   // row g,   k-high
        split2(xf1.z, xf1.w, ah[3], al[3]);   // row g+8, k-high

        const int c0 = ks * 2;
        #pragma unroll
        for (int np = 0; np < 4; np++) {
            int n  = np * 16 + b_row;
            int ch = c0 + b_cadd;
            u32 off = (u32)(n * 128 + (((ch ^ (n & 7)) & 7) << 4));
            u32 bh0, bh1, bh2, bh3, bl0, bl1, bl2, bl3;
            ldmx4(bh0, bh1, bh2, bh3, sb + SM_BHI + off);
            ldmx4(bl0, bl1, bl2, bl3, sb + SM_BLO + off);

            mma_bf16(d[2 * np],     ah, bh0, bh1);   // hi*hi
            mma_bf16(d[2 * np + 1], ah, bh2, bh3);
            mma_bf16(d[2 * np],     ah, bl0, bl1);   // hi*lo
            mma_bf16(d[2 * np + 1], ah, bl2, bl3);
            mma_bf16(d[2 * np],     al, bh0, bh1);   // lo*hi
            mma_bf16(d[2 * np + 1], al, bh2, bh3);
        }

        xf0 = xn0;
        xf1 = xn1;
    }

    // ---- epilogue: n-perm makes nt-pairs contiguous -> STG.128 ----
    const float* sBias = (const float*)(smem + SM_BIAS);
    {
        int r0 = rowBase + wid * 16 + g;
        float* o0 = out + (size_t)r0 * (TT * OO) + (size_t)t * OO;
        float* o1 = o0 + (size_t)8 * (TT * OO);
        #pragma unroll
        for (int m = 0; m < 4; m++) {
            int c = 16 * m + 4 * q;        // true cols c..c+3
            float4 bv = *(const float4*)(sBias + c);
            float4 v0 = { d[2 * m][0] + bv.x, d[2 * m][1] + bv.y,
                          d[2 * m + 1][0] + bv.z, d[2 * m + 1][1] + bv.w };
            float4 v1 = { d[2 * m][2] + bv.x, d[2 * m][3] + bv.y,
                          d[2 * m + 1][2] + bv.z, d[2 * m + 1][3] + bv.w };
            *(float4*)(o0 + c) = v0;       // row r0
            *(float4*)(o1 + c) = v1;       // row r0 + 8
        }
    }
}

extern "C" void kernel_launch(void* const* d_in, const int* in_sizes, int n_in,
                              void* d_out, int out_size)
{
    const float* x    = (const float*)d_in[0];   // 512*1024*64 fp32
    const float* W    = (const float*)d_in[1];   // 1024*64*64 fp32
    const float* bias = (const float*)d_in[2];   // 1024*64 fp32
    float* out        = (float*)d_out;           // 512*1024*64 fp32

    cudaFuncSetAttribute(ParallelLinear_59133109732019_kernel,
                         cudaFuncAttributeMaxDynamicSharedMemorySize, SM_TOTAL);

    dim3 grid(BB / ROWS, TT);   // (8, 1024)
    ParallelLinear_59133109732019_kernel<<<grid, BLOCK, SM_TOTAL>>>(x, W, bias, out);
}

// round 9
// speedup vs baseline: 1.0365x; 1.0365x over previous
#include <cuda_runtime.h>
#include <cuda_bf16.h>
#include <cstdint>

// ParallelLinear: out[b,t,o] = sum_i x[b,t,i] * W[t,o,i] + bias[t,o]
// B=512, T=1024, ISIZE=OSIZE=64, fp32.
// R9: R7 structure (ROWS=128, k/n-permuted fragments, bf16-split mma.sync)
//   + full x tile streamed to smem via cp.async.cg (L1 bypass, huge MLP),
//   mainloop is smem-only (LDS.128 + ldmatrix + MMA): no per-ks DRAM stalls.

#define TT    1024
#define BB    512
#define KK    64
#define OO    64
#define BLOCK 128
#define ROWS  128

typedef unsigned int u32;

// ---- smem byte offsets ----
#define SM_BIAS 0                          // 64 floats = 256 B
#define SM_BHI  256                        // 64 rows * 128 B = 8192
#define SM_BLO  (SM_BHI + OO * 128)        // 8448
#define SM_X    (SM_BLO + OO * 128)        // 16640; x tile 128 rows * 256 B
#define SM_TOTAL (SM_X + ROWS * 256)       // 49408

__device__ __forceinline__ u32 smem_u32(const void* p) {
    u32 a;
    asm("{ .reg .u64 t; cvta.to.shared.u64 t, %1; cvt.u32.u64 %0, t; }" : "=r"(a) : "l"(p));
    return a;
}

// split fp32 pair -> packed bf16x2 hi and lo
__device__ __forceinline__ void split2(float ax, float ay, u32 &hi, u32 &lo) {
    float2 v = { ax, ay };
    __nv_bfloat162 hp = __float22bfloat162_rn(v);
    u32 h = *(u32*)&hp;
    float hx = __uint_as_float(h << 16);
    float hy = __uint_as_float(h & 0xFFFF0000u);
    float2 r = { v.x - hx, v.y - hy };
    __nv_bfloat162 lp = __float22bfloat162_rn(r);
    hi = h;
    lo = *(u32*)&lp;
}

// W staging-write offset with XOR swizzle (row = staged n-position, ip = staged pair idx)
__device__ __forceinline__ u32 stage_off(int row, int ip) {
    return (u32)(row * 128 + ((((ip >> 2) ^ (row & 7)) & 7) << 4) + ((ip & 3) << 2));
}

__device__ __forceinline__ void ldmx4(u32 &r0, u32 &r1, u32 &r2, u32 &r3, u32 addr) {
    asm volatile("ldmatrix.sync.aligned.m8n8.x4.shared.b16 {%0,%1,%2,%3}, [%4];"
                 : "=r"(r0), "=r"(r1), "=r"(r2), "=r"(r3) : "r"(addr));
}

__device__ __forceinline__ void mma_bf16(float* d, const u32* a, u32 b0, u32 b1) {
    asm volatile(
        "mma.sync.aligned.m16n8k16.row.col.f32.bf16.bf16.f32 "
        "{%0,%1,%2,%3}, {%4,%5,%6,%7}, {%8,%9}, {%0,%1,%2,%3};"
        : "+f"(d[0]), "+f"(d[1]), "+f"(d[2]), "+f"(d[3])
        : "r"(a[0]), "r"(a[1]), "r"(a[2]), "r"(a[3]), "r"(b0), "r"(b1));
}

__global__ __launch_bounds__(BLOCK, 4)
void ParallelLinear_59133109732019_kernel(
    const float* __restrict__ x,     // [B, T, 64]
    const float* __restrict__ W,     // [T, 64, 64]  (W[t][o][i])
    const float* __restrict__ bias,  // [T, 64]
    float* __restrict__ out)         // [B, T, 64]
{
    extern __shared__ char smem[];
    const u32 sb = smem_u32(smem);

    const int t       = blockIdx.y;
    const int rowBase = blockIdx.x * ROWS;
    const int tid     = threadIdx.x;
    const int wid     = tid >> 5;
    const int lane    = tid & 31;
    const int g       = lane >> 2;       // row within 8-group
    const int q       = lane & 3;        // fragment column selector

    const size_t xrstride = (size_t)TT * KK;

    // ---- stream x tile to smem via cp.async (chunk-XOR swizzled) ----
    // chunk c (16B) of row r  ->  smem chunk c ^ ((r&3)<<2)
    {
        const char* xg = (const char*)(x + (size_t)rowBase * xrstride + (size_t)t * KK);
        #pragma unroll
        for (int k = 0; k < (ROWS * 16) / BLOCK; k++) {    // 16 chunks per thread
            int idx = k * BLOCK + tid;
            int row = idx >> 4, c = idx & 15;
            u32 dst = sb + SM_X + row * 256 + ((c ^ ((row & 3) << 2)) << 4);
            const char* src = xg + (size_t)row * (xrstride * 4) + c * 16;
            asm volatile("cp.async.cg.shared.global [%0], [%1], 16;"
                         :: "r"(dst), "l"(src) : "memory");
        }
        asm volatile("cp.async.commit_group;" ::: "memory");
    }

    // ---- stage W[t] hi/lo with k-perm (sigma) and n-perm (pi) baked in ----
    {
        const float2* Wg = (const float2*)(W + (size_t)t * (OO * KK));
        #pragma unroll
        for (int k = 0; k < (OO * KK / 2) / BLOCK; k++) {  // 16 iters
            int p = k * BLOCK + tid;
            int o = p >> 5, ip = p & 31;                   // o row, source i-pair
            u32 hi, lo;
            float2 v = Wg[p];
            split2(v.x, v.y, hi, lo);
            // k-perm: pair cp within 16-block -> cp' = (cp&1)*4 + (cp>>1)
            int blk = ip >> 3, cp = ip & 7;
            int ipp = (blk << 3) | (((cp & 1) << 2) | (cp >> 1));
            // n-perm: o = 16m + 4q + 2b + j -> row' = 16m + 8b + 2q + j
            int m = o >> 4, qq = (o >> 2) & 3, bb = (o >> 1) & 1, j = o & 1;
            int rowp = (m << 4) | (bb << 3) | (qq << 1) | j;
            u32 off = stage_off(rowp, ipp);
            *(u32*)(smem + SM_BHI + off) = hi;
            *(u32*)(smem + SM_BLO + off) = lo;
        }
        if (tid < OO) ((float*)(smem + SM_BIAS))[tid] = bias[(size_t)t * OO + tid];
    }

    asm volatile("cp.async.wait_group 0;" ::: "memory");
    __syncthreads();

    // ---- accumulators: 2 m-tiles x 8 n-tiles x 4 fp32 ----
    float d[2][8][4];
    #pragma unroll
    for (int mt = 0; mt < 2; mt++)
        #pragma unroll
        for (int nt = 0; nt < 8; nt++)
            #pragma unroll
            for (int e = 0; e < 4; e++) d[mt][nt][e] = 0.0f;

    // B-fragment ldmatrix lane->address components
    const int b_row  = (lane & 7) + ((lane >> 4) << 3);
    const int b_cadd = (lane >> 3) & 1;

    // x fragment smem rows for this lane (row & 3 == g & 3 since bases are mult of 8)
    const int xr0 = wid * 32 + g;               // mt=0, low 8-group
    const int cxor = (g & 3) << 2;

    #pragma unroll
    for (int ks = 0; ks < 4; ks++) {
        // fragment chunk index: c = 4*ks + q, swizzled by row
        const int cc = ((4 * ks + q) ^ cxor) << 4;

        u32 ah[2][4], al[2][4];
        #pragma unroll
        for (int mt = 0; mt < 2; mt++) {
            int ra = xr0 + mt * 16;
            float4 f0 = *(const float4*)(smem + SM_X + ra * 256 + cc);        // row g
            float4 f1 = *(const float4*)(smem + SM_X + (ra + 8) * 256 + cc);  // row g+8
            split2(f0.x, f0.y, ah[mt][0], al[mt][0]);   // k-low
            split2(f1.x, f1.y, ah[mt][1], al[mt][1]);
            split2(f0.z, f0.w, ah[mt][2], al[mt][2]);   // k-high
            split2(f1.z, f1.w, ah[mt][3], al[mt][3]);
        }

        const int c0 = ks * 2;
        #pragma unroll
        for (int np = 0; np < 4; np++) {
            int n  = np * 16 + b_row;
            int ch = c0 + b_cadd;
            u32 off = (u32)(n * 128 + (((ch ^ (n & 7)) & 7) << 4));
            u32 bh0, bh1, bh2, bh3, bl0, bl1, bl2, bl3;
            ldmx4(bh0, bh1, bh2, bh3, sb + SM_BHI + off);
            ldmx4(bl0, bl1, bl2, bl3, sb + SM_BLO + off);

            #pragma unroll
            for (int mt = 0; mt < 2; mt++) {
                mma_bf16(d[mt][2 * np],     ah[mt], bh0, bh1);   // hi*hi
                mma_bf16(d[mt][2 * np + 1], ah[mt], bh2, bh3);
                mma_bf16(d[mt][2 * np],     ah[mt], bl0, bl1);   // hi*lo
                mma_bf16(d[mt][2 * np + 1], ah[mt], bl2, bl3);
                mma_bf16(d[mt][2 * np],     al[mt], bh0, bh1);   // lo*hi
                mma_bf16(d[mt][2 * np + 1], al[mt], bh2, bh3);
            }
        }
    }

    // ---- epilogue: n-perm makes nt-pairs contiguous -> STG.128 ----
    const float* sBias = (const float*)(smem + SM_BIAS);
    #pragma unroll
    for (int mt = 0; mt < 2; mt++) {
        int r0 = rowBase + wid * 32 + mt * 16 + g;
        float* o0 = out + (size_t)r0 * (TT * OO) + (size_t)t * OO;
        float* o1 = o0 + (size_t)8 * (TT * OO);
        #pragma unroll
        for (int m = 0; m < 4; m++) {
            int c = 16 * m + 4 * q;        // true cols c..c+3
            float4 bv = *(const float4*)(sBias + c);
            float4 v0 = { d[mt][2 * m][0] + bv.x, d[mt][2 * m][1] + bv.y,
                          d[mt][2 * m + 1][0] + bv.z, d[mt][2 * m + 1][1] + bv.w };
            float4 v1 = { d[mt][2 * m][2] + bv.x, d[mt][2 * m][3] + bv.y,
                          d[mt][2 * m + 1][2] + bv.z, d[mt][2 * m + 1][3] + bv.w };
            *(float4*)(o0 + c) = v0;       // row r0
            *(float4*)(o1 + c) = v1;       // row r0 + 8
        }
    }
}

extern "C" void kernel_launch(void* const* d_in, const int* in_sizes, int n_in,
                              void* d_out, int out_size)
{
    const float* x    = (const float*)d_in[0];   // 512*1024*64 fp32
    const float* W    = (const float*)d_in[1];   // 1024*64*64 fp32
    const float* bias = (const float*)d_in[2];   // 1024*64 fp32
    float* out        = (float*)d_out;           // 512*1024*64 fp32

    cudaFuncSetAttribute(ParallelLinear_59133109732019_kernel,
                         cudaFuncAttributeMaxDynamicSharedMemorySize, SM_TOTAL);

    dim3 grid(BB / ROWS, TT);   // (4, 1024)
    ParallelLinear_59133109732019_kernel<<<grid, BLOCK, SM_TOTAL>>>(x, W, bias, out);
}